// round 15
// baseline (speedup 1.0000x reference)
#include <cuda_runtime.h>
#include <math.h>

#define B_DIM 64
#define K_DIM 128
#define H_DIM 64
#define W_DIM 64
#define PLANE (H_DIM * W_DIM)          // 4096 floats
#define N_PLANES (B_DIM * K_DIM)       // 8192
#define N_BOXES 256
#define ALPHA 1.0f
#define BETA 0.5f
#define NPART 32
#define PART_STRIDE 32                 // 128B between accumulator slots
#define MAX_BOX_HITS 8

// Zero-initialized device globals; finalize kernel resets them each run.
__device__ float g_cls_parts[NPART * PART_STRIDE];
__device__ float g_loc_parts[NPART * PART_STRIDE];

__device__ __forceinline__ float softplus_f(float x) {
    float ax = fabsf(x);
    return log1pf(expf(-ax)) + fmaxf(x, 0.0f);
}

// One CTA per (b,k) plane. Uniform wave: every block runs the identical
// streaming max pass; the rare block whose plane is referenced by a box
// additionally re-reads its (L1-resident) plane for the loc sums.
__global__ __launch_bounds__(256) void main_kernel(
    const float* __restrict__ cams,
    const float* __restrict__ concepts_gt,
    const int* __restrict__ box_b,
    const int* __restrict__ box_c,
    const int* __restrict__ y0v,
    const int* __restrict__ y1v,
    const int* __restrict__ x0v,
    const int* __restrict__ x1v)
{
    int plane = blockIdx.x;
    const float4* p = reinterpret_cast<const float4*>(cams + (size_t)plane * PLANE);

    int t = threadIdx.x;
    int wid = t >> 5, lid = t & 31;

    __shared__ float s0[8], s1[8];
    __shared__ int s_cnt;
    __shared__ int s_list[MAX_BOX_HITS];

    if (t == 0) s_cnt = 0;

    // ---- streaming max pass (proven shape) ----
    float m = -INFINITY;
#pragma unroll
    for (int i = 0; i < 4; i++) {
        float4 v = p[i * 256 + t];
        m = fmaxf(m, fmaxf(fmaxf(v.x, v.y), fmaxf(v.z, v.w)));
    }

    // ---- box matching: thread t tests box t (expected hits: 1 per 32 blocks) ----
    if (t < N_BOXES) {
        if (box_b[t] * K_DIM + box_c[t] == plane) {
            int pos = atomicAdd(&s_cnt, 1);
            if (pos < MAX_BOX_HITS) s_list[pos] = t;
        }
    }

#pragma unroll
    for (int off = 16; off > 0; off >>= 1)
        m = fmaxf(m, __shfl_xor_sync(0xFFFFFFFFu, m, off));
    if (lid == 0) s0[wid] = m;
    __syncthreads();                 // publishes s0, s_cnt, s_list

    if (t == 0) {
        float bm = s0[0];
#pragma unroll
        for (int w = 1; w < 8; w++) bm = fmaxf(bm, s0[w]);
        float y = concepts_gt[plane];
        float bce = y * softplus_f(-bm) + (1.0f - y) * softplus_f(bm);
        atomicAdd(&g_cls_parts[(plane & (NPART - 1)) * PART_STRIDE], bce);
    }

    // ---- loc pass for matched boxes: re-reads plane from L1 ----
    int nbox = min(s_cnt, MAX_BOX_HITS);   // uniform across block (post-bar)
    for (int bi = 0; bi < nbox; bi++) {
        __syncthreads();                   // protect s0/s1 reuse
        int box = s_list[bi];
        int y0 = y0v[box], y1 = y1v[box], x0 = x0v[box], x1 = x1v[box];

        float inside = 0.0f, outside = 0.0f;
#pragma unroll
        for (int i = 0; i < 4; i++) {
            int u = i * 256 + t;
            float4 v = p[u];               // L1 hit: plane just streamed
            int row = u >> 4;              // 16 float4 per row (W=64)
            int col0 = (u & 15) << 2;
            bool rin = (row >= y0) && (row < y1);
            float vals[4] = {v.x, v.y, v.z, v.w};
#pragma unroll
            for (int j = 0; j < 4; j++) {
                int col = col0 + j;
                float e = __expf(-vals[j]);
                float s = __fdividef(1.0f, 1.0f + e);
                bool in = rin && (col >= x0) && (col < x1);
                float d = s - 1.0f;
                if (in) inside += d * d;
                else    outside += s * s;
            }
        }
#pragma unroll
        for (int off = 16; off > 0; off >>= 1) {
            inside  += __shfl_xor_sync(0xFFFFFFFFu, inside, off);
            outside += __shfl_xor_sync(0xFFFFFFFFu, outside, off);
        }
        if (lid == 0) { s0[wid] = inside; s1[wid] = outside; }
        __syncthreads();
        if (t == 0) {
            float ti = 0.0f, to = 0.0f;
#pragma unroll
            for (int w = 0; w < 8; w++) { ti += s0[w]; to += s1[w]; }
            float area = (float)((y1 - y0) * (x1 - x0));
            const float eps = 1e-6f;
            float loss = ti / (area + eps) + to / ((float)PLANE - area + eps);
            atomicAdd(&g_loc_parts[(box & (NPART - 1)) * PART_STRIDE], loss);
        }
    }
}

// PDL secondary: launch overlaps main kernel; grid-dependency sync waits for
// its completion (and memory visibility) before reading the parts.
__global__ void finalize_kernel(float* __restrict__ out) {
    cudaGridDependencySynchronize();

    int lid = threadIdx.x;   // 32 threads
    float cls = g_cls_parts[lid * PART_STRIDE];
    float loc = g_loc_parts[lid * PART_STRIDE];
    g_cls_parts[lid * PART_STRIDE] = 0.0f;
    g_loc_parts[lid * PART_STRIDE] = 0.0f;
#pragma unroll
    for (int off = 16; off > 0; off >>= 1) {
        cls += __shfl_xor_sync(0xFFFFFFFFu, cls, off);
        loc += __shfl_xor_sync(0xFFFFFFFFu, loc, off);
    }
    if (lid == 0)
        out[0] = ALPHA * (cls / (float)N_PLANES) + BETA * (loc / (float)N_BOXES);
}

extern "C" void kernel_launch(void* const* d_in, const int* in_sizes, int n_in,
                              void* d_out, int out_size) {
    const float* cams        = (const float*)d_in[0];
    const float* concepts_gt = (const float*)d_in[1];
    const int*   box_b       = (const int*)d_in[2];
    const int*   box_c       = (const int*)d_in[3];
    const int*   y0          = (const int*)d_in[4];
    const int*   y1          = (const int*)d_in[5];
    const int*   x0          = (const int*)d_in[6];
    const int*   x1          = (const int*)d_in[7];
    float* out = (float*)d_out;

    main_kernel<<<N_PLANES, 256>>>(cams, concepts_gt, box_b, box_c, y0, y1, x0, x1);

    cudaLaunchConfig_t cfg = {};
    cfg.gridDim  = dim3(1, 1, 1);
    cfg.blockDim = dim3(32, 1, 1);
    cfg.dynamicSmemBytes = 0;
    cfg.stream = 0;
    cudaLaunchAttribute attr;
    attr.id = cudaLaunchAttributeProgrammaticStreamSerialization;
    attr.val.programmaticStreamSerializationAllowed = 1;
    cfg.attrs = &attr;
    cfg.numAttrs = 1;
    cudaLaunchKernelEx(&cfg, finalize_kernel, out);
}

// round 16
// speedup vs baseline: 1.0178x; 1.0178x over previous
#include <cuda_runtime.h>
#include <math.h>

#define B_DIM 64
#define K_DIM 128
#define H_DIM 64
#define W_DIM 64
#define PLANE (H_DIM * W_DIM)          // 4096 floats
#define N_PLANES (B_DIM * K_DIM)       // 8192
#define N_BOXES 256
#define N_BLOCKS (N_PLANES + N_BOXES)  // 8448
#define ALPHA 1.0f
#define BETA 0.5f
#define NPART 32
#define PART_STRIDE 32                 // 128B between accumulator slots

// Zero-initialized device globals; finalize kernel resets them each run.
__device__ float g_cls_parts[NPART * PART_STRIDE];
__device__ float g_loc_parts[NPART * PART_STRIDE];

__device__ __forceinline__ float softplus_f(float x) {
    float ax = fabsf(x);
    return log1pf(expf(-ax)) + fmaxf(x, 0.0f);
}

// Kernel 1: loc blocks [0,256) then cls blocks [256,8448).
__global__ __launch_bounds__(256) void main_kernel(
    const float* __restrict__ cams,
    const float* __restrict__ concepts_gt,
    const int* __restrict__ box_b,
    const int* __restrict__ box_c,
    const int* __restrict__ y0v,
    const int* __restrict__ y1v,
    const int* __restrict__ x0v,
    const int* __restrict__ x1v)
{
    // Fire PDL trigger immediately: once all blocks have launched, the
    // dependent finalize kernel is dispatched (overlapping its launch
    // latency with this kernel's execution).
    cudaTriggerProgrammaticLaunchCompletion();

    int t = threadIdx.x;
    int wid = t >> 5, lid = t & 31;
    __shared__ float s0[8], s1[8];

    if (blockIdx.x < N_BOXES) {
        // ---------------- loc block: one box ----------------
        int box = blockIdx.x;
        int b = box_b[box];
        int c = box_c[box];
        int y0 = y0v[box], y1 = y1v[box], x0 = x0v[box], x1 = x1v[box];

        const float4* p = reinterpret_cast<const float4*>(
            cams + ((size_t)b * K_DIM + c) * PLANE);

        float inside = 0.0f, outside = 0.0f;
#pragma unroll
        for (int i = 0; i < 4; i++) {
            int u = i * 256 + t;        // float4 index within plane [0,1024)
            float4 v = p[u];
            int row = u >> 4;           // 16 float4 per row (W=64)
            int col0 = (u & 15) << 2;
            float vals[4] = {v.x, v.y, v.z, v.w};
            bool rin = (row >= y0) && (row < y1);
#pragma unroll
            for (int j = 0; j < 4; j++) {
                int col = col0 + j;
                float e = __expf(-vals[j]);
                float s = __fdividef(1.0f, 1.0f + e);
                bool in = rin && (col >= x0) && (col < x1);
                float d = s - 1.0f;
                if (in) inside += d * d;
                else    outside += s * s;
            }
        }
#pragma unroll
        for (int off = 16; off > 0; off >>= 1) {
            inside  += __shfl_xor_sync(0xFFFFFFFFu, inside, off);
            outside += __shfl_xor_sync(0xFFFFFFFFu, outside, off);
        }
        if (lid == 0) { s0[wid] = inside; s1[wid] = outside; }
        __syncthreads();
        if (t == 0) {
            float ti = 0.0f, to = 0.0f;
#pragma unroll
            for (int w = 0; w < 8; w++) { ti += s0[w]; to += s1[w]; }
            float area = (float)((y1 - y0) * (x1 - x0));
            const float eps = 1e-6f;
            float loss = ti / (area + eps) + to / ((float)PLANE - area + eps);
            atomicAdd(&g_loc_parts[(box & (NPART - 1)) * PART_STRIDE], loss);
        }
    } else {
        // ---------------- cls block: one (b,k) plane ----------------
        int plane = blockIdx.x - N_BOXES;
        const float4* p = reinterpret_cast<const float4*>(cams + (size_t)plane * PLANE);

        float m = -INFINITY;
#pragma unroll
        for (int i = 0; i < 4; i++) {
            float4 v = p[i * 256 + t];
            m = fmaxf(m, fmaxf(fmaxf(v.x, v.y), fmaxf(v.z, v.w)));
        }
#pragma unroll
        for (int off = 16; off > 0; off >>= 1)
            m = fmaxf(m, __shfl_xor_sync(0xFFFFFFFFu, m, off));
        if (lid == 0) s0[wid] = m;
        __syncthreads();
        if (t == 0) {
            float bm = s0[0];
#pragma unroll
            for (int w = 1; w < 8; w++) bm = fmaxf(bm, s0[w]);
            float y = concepts_gt[plane];
            float bce = y * softplus_f(-bm) + (1.0f - y) * softplus_f(bm);
            atomicAdd(&g_cls_parts[(plane & (NPART - 1)) * PART_STRIDE], bce);
        }
    }
}

// PDL secondary: dispatched early (trigger), blocks on grid dependency until
// main_kernel completes with memory visibility, then reduces and writes out.
__global__ void finalize_kernel(float* __restrict__ out) {
    cudaGridDependencySynchronize();

    int lid = threadIdx.x;   // 32 threads
    float cls = g_cls_parts[lid * PART_STRIDE];
    float loc = g_loc_parts[lid * PART_STRIDE];
    g_cls_parts[lid * PART_STRIDE] = 0.0f;
    g_loc_parts[lid * PART_STRIDE] = 0.0f;
#pragma unroll
    for (int off = 16; off > 0; off >>= 1) {
        cls += __shfl_xor_sync(0xFFFFFFFFu, cls, off);
        loc += __shfl_xor_sync(0xFFFFFFFFu, loc, off);
    }
    if (lid == 0)
        out[0] = ALPHA * (cls / (float)N_PLANES) + BETA * (loc / (float)N_BOXES);
}

extern "C" void kernel_launch(void* const* d_in, const int* in_sizes, int n_in,
                              void* d_out, int out_size) {
    const float* cams        = (const float*)d_in[0];
    const float* concepts_gt = (const float*)d_in[1];
    const int*   box_b       = (const int*)d_in[2];
    const int*   box_c       = (const int*)d_in[3];
    const int*   y0          = (const int*)d_in[4];
    const int*   y1          = (const int*)d_in[5];
    const int*   x0          = (const int*)d_in[6];
    const int*   x1          = (const int*)d_in[7];
    float* out = (float*)d_out;

    main_kernel<<<N_BLOCKS, 256>>>(cams, concepts_gt, box_b, box_c, y0, y1, x0, x1);

    // PDL launch of the finalizer: primary's trigger lets this dispatch early.
    cudaLaunchConfig_t cfg = {};
    cfg.gridDim  = dim3(1, 1, 1);
    cfg.blockDim = dim3(32, 1, 1);
    cfg.dynamicSmemBytes = 0;
    cfg.stream = 0;
    cudaLaunchAttribute attr;
    attr.id = cudaLaunchAttributeProgrammaticStreamSerialization;
    attr.val.programmaticStreamSerializationAllowed = 1;
    cfg.attrs = &attr;
    cfg.numAttrs = 1;
    cudaLaunchKernelEx(&cfg, finalize_kernel, out);
}